// round 6
// baseline (speedup 1.0000x reference)
#include <cuda_runtime.h>
#include <cuda_bf16.h>
#include <cstdint>

// Problem constants
#define DM   1024        // d_model
#define NH   16          // heads
#define DH   64          // head dim
#define BB   2           // batch
#define SS   2048        // seq len
#define MT   (BB*SS)     // total rows = 4096

typedef unsigned long long ull;

// ---------------------------------------------------------------------------
// Scratch (device globals; no allocation allowed)
// ---------------------------------------------------------------------------
__device__ float g_q[BB*NH*SS*DH];               // [B,H,S,Dh] fp32
__device__ float g_k[BB*NH*SS*DH];
__device__ float g_v[BB*NH*SS*DH];
__device__ __nv_bfloat16 g_xhi[MT*DM], g_xlo[MT*DM];        // X split
__device__ __nv_bfloat16 g_wth[4][DM*DM], g_wtl[4][DM*DM];  // W^T splits (q,k,v,o)
__device__ __nv_bfloat16 g_ahi[MT*DM], g_alo[MT*DM];        // attention out split

// ---------------------------------------------------------------------------
// packed f32x2 helpers (attention inner loops)
// ---------------------------------------------------------------------------
__device__ __forceinline__ ull pack2(float lo, float hi) {
    ull r; asm("mov.b64 %0, {%1, %2};" : "=l"(r) : "f"(lo), "f"(hi)); return r;
}
__device__ __forceinline__ ull dup2(float v) { return pack2(v, v); }
__device__ __forceinline__ void fma2(ull& d, ull a, ull b) {
    asm("fma.rn.f32x2 %0, %1, %2, %0;" : "+l"(d) : "l"(a), "l"(b));
}
__device__ __forceinline__ void mul2(ull& d, ull a) {
    asm("mul.rn.f32x2 %0, %0, %1;" : "+l"(d) : "l"(a));
}
__device__ __forceinline__ float2 unpk2(ull v) {
    float2 r; asm("mov.b64 {%0, %1}, %2;" : "=f"(r.x), "=f"(r.y) : "l"(v)); return r;
}

__device__ __forceinline__ uint32_t smem_u32(const void* p) {
    uint32_t a;
    asm("{ .reg .u64 t; cvta.to.shared.u64 t, %1; cvt.u32.u64 %0, t; }" : "=r"(a) : "l"(p));
    return a;
}

__device__ __forceinline__ void bsplit(float x, __nv_bfloat16& h, __nv_bfloat16& l) {
    h = __float2bfloat16(x);
    l = __float2bfloat16(x - __bfloat162float(h));
}

// ---------------------------------------------------------------------------
// mma.sync / ldmatrix / cp.async primitives (sm_80+ features; compile at
// compute_103 — NO tcgen05, which the harness's PTX target rejects)
// ---------------------------------------------------------------------------
#define CPA(dst, src) asm volatile("cp.async.cg.shared.global [%0], [%1], 16;" :: "r"(dst), "l"(src))
#define CPC() asm volatile("cp.async.commit_group;" ::: "memory")
#define CPW(n) asm volatile("cp.async.wait_group %0;" :: "n"(n) : "memory")

__device__ __forceinline__ void ldm4(uint32_t* r, uint32_t addr) {
    asm volatile("ldmatrix.sync.aligned.m8n8.x4.shared.b16 {%0,%1,%2,%3}, [%4];"
                 : "=r"(r[0]), "=r"(r[1]), "=r"(r[2]), "=r"(r[3]) : "r"(addr));
}
__device__ __forceinline__ void mma_bf16(float* d, const uint32_t* a,
                                         uint32_t b0, uint32_t b1) {
    asm volatile(
        "mma.sync.aligned.m16n8k16.row.col.f32.bf16.bf16.f32 "
        "{%0,%1,%2,%3}, {%4,%5,%6,%7}, {%8,%9}, {%0,%1,%2,%3};"
        : "+f"(d[0]), "+f"(d[1]), "+f"(d[2]), "+f"(d[3])
        : "r"(a[0]), "r"(a[1]), "r"(a[2]), "r"(a[3]), "r"(b0), "r"(b1));
}

// ---------------------------------------------------------------------------
// Prep: split X into bf16 hi/lo
// ---------------------------------------------------------------------------
__global__ void __launch_bounds__(256) split_x(const float* __restrict__ X)
{
    const int i = (blockIdx.x * 256 + threadIdx.x) * 4;
    float4 v = *(const float4*)(X + i);
    __nv_bfloat16 h0, h1, h2, h3, l0, l1, l2, l3;
    bsplit(v.x, h0, l0); bsplit(v.y, h1, l1);
    bsplit(v.z, h2, l2); bsplit(v.w, h3, l3);
    *(__nv_bfloat162*)(g_xhi + i)     = __nv_bfloat162(h0, h1);
    *(__nv_bfloat162*)(g_xhi + i + 2) = __nv_bfloat162(h2, h3);
    *(__nv_bfloat162*)(g_xlo + i)     = __nv_bfloat162(l0, l1);
    *(__nv_bfloat162*)(g_xlo + i + 2) = __nv_bfloat162(l2, l3);
}

// ---------------------------------------------------------------------------
// Prep: transpose W [K,N] -> Wt [N,K], split bf16 hi/lo.  z selects matrix.
// ---------------------------------------------------------------------------
__global__ void __launch_bounds__(256) wsplit(
    const float* __restrict__ Wq, const float* __restrict__ Wk,
    const float* __restrict__ Wv, const float* __restrict__ Wo)
{
    __shared__ float t[32][33];
    const int z = blockIdx.z;
    const float* src = (z == 0) ? Wq : (z == 1) ? Wk : (z == 2) ? Wv : Wo;
    const int tx = threadIdx.x & 31;
    const int ty = threadIdx.x >> 5;
    const int n0 = blockIdx.x * 32;
    const int k0 = blockIdx.y * 32;
#pragma unroll
    for (int i = 0; i < 4; i++)
        t[ty + 8 * i][tx] = src[(size_t)(k0 + ty + 8 * i) * DM + n0 + tx];
    __syncthreads();
#pragma unroll
    for (int i = 0; i < 4; i++) {
        const int n = n0 + ty + 8 * i;
        const int k = k0 + tx;
        __nv_bfloat16 h, l;
        bsplit(t[tx][ty + 8 * i], h, l);
        g_wth[z][(size_t)n * DM + k] = h;
        g_wtl[z][(size_t)n * DM + k] = l;
    }
}

// ---------------------------------------------------------------------------
// mma.sync GEMM: C = A @ B^T via bf16-split (hh + hl + lh, fp32 acc).
// CTA 128x128, BK=32, 8 warps (2m x 4n), warp 64x32, cp.async double buffer.
// Smem row stride 40 bf16 (80B, odd multiple of 16B -> conflict-free ldmatrix).
// ---------------------------------------------------------------------------
#define BK      32
#define SAST    40                       // bf16 per smem row (80 bytes)
#define TILE_B  (128 * SAST * 2)         // 10240 B per tile
#define STAGE_B (4 * TILE_B)             // Ahi, Alo, Bhi, Blo = 40960 B
#define SMEM_MMA (2 * STAGE_B)           // 81920 B

template<bool SPLIT_HEAD>
__device__ __forceinline__ void gemm_mma_body(
    const __nv_bfloat16* __restrict__ Ah, const __nv_bfloat16* __restrict__ Al,
    const __nv_bfloat16* __restrict__ Bh, const __nv_bfloat16* __restrict__ Bl,
    const float* __restrict__ bias, float* __restrict__ out)
{
    extern __shared__ char smem[];
    const uint32_t sb = smem_u32(smem);
    const int tid  = threadIdx.x;
    const int lane = tid & 31;
    const int wid  = tid >> 5;
    const int wm   = wid & 1;           // 2 warp rows
    const int wn   = wid >> 1;          // 4 warp cols
    const int m0   = wm * 64;
    const int n0   = wn * 32;
    const int rowBase = blockIdx.y * 128;
    const int colBase = blockIdx.x * 128;

    const __nv_bfloat16* srcs[4] = {
        Ah + (size_t)rowBase * DM, Al + (size_t)rowBase * DM,
        Bh + (size_t)colBase * DM, Bl + (size_t)colBase * DM };

    float acc[4][4][4];
#pragma unroll
    for (int i = 0; i < 4; i++)
#pragma unroll
        for (int j = 0; j < 4; j++)
#pragma unroll
            for (int k = 0; k < 4; k++) acc[i][j][k] = 0.f;

    auto load_stage = [&](int kt, int buf) {
#pragma unroll
        for (int i = 0; i < 8; i++) {
            const int id = tid + 256 * i;          // 0..2047 16B chunks
            const int t  = id >> 9;                // tile 0..3
            const int rr = (id >> 2) & 127;        // row 0..127
            const int cc = id & 3;                 // 16B chunk in row
            const __nv_bfloat16* s = srcs[t] + (size_t)rr * DM + kt * BK + cc * 8;
            const uint32_t d = sb + buf * STAGE_B + t * TILE_B + rr * 80 + cc * 16;
            CPA(d, s);
        }
    };

    load_stage(0, 0); CPC();

    const int lrow = lane & 15;
    const int lchk = (lane >> 4) * 16;

    for (int kt = 0; kt < DM / BK; kt++) {
        if (kt + 1 < DM / BK) { load_stage(kt + 1, (kt + 1) & 1); CPC(); CPW(1); }
        else                  { CPW(0); }
        __syncthreads();

        const uint32_t base = sb + (kt & 1) * STAGE_B;
        const uint32_t aHi = base;
        const uint32_t aLo = base + TILE_B;
        const uint32_t bHi = base + 2 * TILE_B;
        const uint32_t bLo = base + 3 * TILE_B;

#pragma unroll
        for (int sub = 0; sub < 2; sub++) {
            const uint32_t co = sub * 32 + lchk;
            uint32_t a[4][4], bh2[2][4], bl2[2][4];
#pragma unroll
            for (int mt = 0; mt < 4; mt++)
                ldm4(a[mt], aHi + (m0 + mt * 16 + lrow) * 80 + co);
#pragma unroll
            for (int p = 0; p < 2; p++)
                ldm4(bh2[p], bHi + (n0 + p * 16 + lrow) * 80 + co);
            // hi*hi
#pragma unroll
            for (int mt = 0; mt < 4; mt++)
#pragma unroll
                for (int nt = 0; nt < 4; nt++)
                    mma_bf16(acc[mt][nt], a[mt],
                             bh2[nt >> 1][nt & 1], bh2[nt >> 1][2 + (nt & 1)]);
            // hi*lo
#pragma unroll
            for (int p = 0; p < 2; p++)
                ldm4(bl2[p], bLo + (n0 + p * 16 + lrow) * 80 + co);
#pragma unroll
            for (int mt = 0; mt < 4; mt++)
#pragma unroll
                for (int nt = 0; nt < 4; nt++)
                    mma_bf16(acc[mt][nt], a[mt],
                             bl2[nt >> 1][nt & 1], bl2[nt >> 1][2 + (nt & 1)]);
            // lo*hi  (reuse a[] registers for A_lo)
#pragma unroll
            for (int mt = 0; mt < 4; mt++)
                ldm4(a[mt], aLo + (m0 + mt * 16 + lrow) * 80 + co);
#pragma unroll
            for (int mt = 0; mt < 4; mt++)
#pragma unroll
                for (int nt = 0; nt < 4; nt++)
                    mma_bf16(acc[mt][nt], a[mt],
                             bh2[nt >> 1][nt & 1], bh2[nt >> 1][2 + (nt & 1)]);
        }
        __syncthreads();
    }

    // epilogue: d0,d1 -> (row g, col q*2..+1); d2,d3 -> row g+8
    const int g = lane >> 2;
    const int q = lane & 3;
#pragma unroll
    for (int mt = 0; mt < 4; mt++)
#pragma unroll
        for (int nt = 0; nt < 4; nt++) {
            const int c = colBase + n0 + nt * 8 + q * 2;
#pragma unroll
            for (int half = 0; half < 2; half++) {
                const int r = rowBase + m0 + mt * 16 + g + half * 8;
                float2 v = make_float2(acc[mt][nt][half * 2], acc[mt][nt][half * 2 + 1]);
                if (SPLIT_HEAD) {
                    v.x += bias[c]; v.y += bias[c + 1];
                    const int h  = c >> 6;
                    const int dh = c & 63;
                    const int b  = r >> 11;
                    const int s  = r & 2047;
                    *(float2*)&out[((size_t)((b * NH + h) * SS) + s) * DH + dh] = v;
                } else {
                    *(float2*)&out[(size_t)r * DM + c] = v;
                }
            }
        }
}

__global__ void __launch_bounds__(256, 2) qkv_gemm_mma(
    const float* __restrict__ bq, const float* __restrict__ bk,
    const float* __restrict__ bv)
{
    const int z = blockIdx.z;
    const float* bias = (z == 0) ? bq : (z == 1) ? bk : bv;
    float* out = (z == 0) ? g_q : (z == 1) ? g_k : g_v;
    gemm_mma_body<true>(g_xhi, g_xlo, g_wth[z], g_wtl[z], bias, out);
}

__global__ void __launch_bounds__(256, 2) out_gemm_mma(float* __restrict__ out)
{
    gemm_mma_body<false>(g_ahi, g_alo, g_wth[3], g_wtl[3], nullptr, out);
}

// ---------------------------------------------------------------------------
// Flash attention (causal, online softmax), FFMA2 register-blocked.
// Br=128, Bc=64, 256 threads; epilogue writes bf16 hi/lo for the O-projection.
// ---------------------------------------------------------------------------
#define QST 132
#define KST 68

__global__ void __launch_bounds__(256, 2) attn_kernel()
{
    extern __shared__ float sm[];
    float* Qt = sm;                       // 64 x 132 (d-major, transposed)
    float* Kt = sm + 64 * QST;            // 64 x 68
    float* Vs = Kt + 64 * KST;            // 64 x 68
    float* Pt = Vs + 64 * KST;            // 64 x 132

    const int tid = threadIdx.x;
    const int qb  = (gridDim.x - 1) - blockIdx.x;
    const int h   = blockIdx.y;
    const int b   = blockIdx.z;
    const int tx  = tid & 15;
    const int ty  = tid >> 4;

    const size_t head_off = (size_t)(b * NH + h) * SS * DH;
    const float* qbase = g_q + head_off;
    const float* kbase = g_k + head_off;
    const float* vbase = g_v + head_off;
    const int q0 = qb * 128;

#pragma unroll
    for (int i = 0; i < 8; i++) {
        const int f  = tid + 256 * i;
        const int r  = f >> 4;
        const int c4 = (f & 15) << 2;
        float4 v = *(const float4*)(qbase + (size_t)(q0 + r) * DH + c4);
        Qt[(c4 + 0) * QST + r] = v.x * 0.125f;
        Qt[(c4 + 1) * QST + r] = v.y * 0.125f;
        Qt[(c4 + 2) * QST + r] = v.z * 0.125f;
        Qt[(c4 + 3) * QST + r] = v.w * 0.125f;
    }

    ull accO[4][4];
#pragma unroll
    for (int i = 0; i < 4; i++)
#pragma unroll
        for (int j = 0; j < 4; j++) accO[i][j] = 0ull;
    float m[8], l[8];
#pragma unroll
    for (int i = 0; i < 8; i++) { m[i] = -1e30f; l[i] = 0.f; }

    const int kb_end = 2 * qb + 1;
    for (int kb = 0; kb <= kb_end; kb++) {
        __syncthreads();
        const int k0 = kb * 64;
#pragma unroll
        for (int i = 0; i < 4; i++) {
            const int f  = tid + 256 * i;
            const int r  = f >> 4;
            const int c4 = (f & 15) << 2;
            const size_t goff = (size_t)(k0 + r) * DH + c4;
            float4 kv = *(const float4*)(kbase + goff);
            Kt[(c4 + 0) * KST + r] = kv.x;
            Kt[(c4 + 1) * KST + r] = kv.y;
            Kt[(c4 + 2) * KST + r] = kv.z;
            Kt[(c4 + 3) * KST + r] = kv.w;
            *(float4*)&Vs[r * KST + c4] = *(const float4*)(vbase + goff);
        }
        __syncthreads();

        ull accS[4][4];
#pragma unroll
        for (int i = 0; i < 4; i++)
#pragma unroll
            for (int j = 0; j < 4; j++) accS[i][j] = 0ull;

#pragma unroll 4
        for (int d = 0; d < 64; d++) {
            const float* qr = &Qt[d * QST + ty * 8];
            ulonglong2 t0 = *(const ulonglong2*)qr;
            ulonglong2 t1 = *(const ulonglong2*)(qr + 4);
            ull a2[4] = { t0.x, t0.y, t1.x, t1.y };
            float4 kv = *(const float4*)&Kt[d * KST + tx * 4];
            ull k2[4] = { dup2(kv.x), dup2(kv.y), dup2(kv.z), dup2(kv.w) };
#pragma unroll
            for (int i = 0; i < 4; i++)
#pragma unroll
                for (int j = 0; j < 4; j++)
                    fma2(accS[i][j], a2[i], k2[j]);
        }

        const int rel = k0 - q0;
        float mt[8];
#pragma unroll
        for (int i = 0; i < 8; i++) mt[i] = -1e30f;

        if (rel >= -63) {
#pragma unroll
            for (int i2 = 0; i2 < 4; i2++) {
                const int re = ty * 8 + 2 * i2;
#pragma unroll
                for (int j = 0; j < 4; j++) {
                    float2 s = unpk2(accS[i2][j]);
                    const int c = rel + tx * 4 + j;
                    if (c > re)     s.x = -1e30f;
                    if (c > re + 1) s.y = -1e30f;
                    accS[i2][j] = pack2(s.x, s.y);
                    mt[2 * i2]     = fmaxf(mt[2 * i2],     s.x);
                    mt[2 * i2 + 1] = fmaxf(mt[2 * i2 + 1], s.y);
                }
            }
        } else {
#pragma unroll
            for (int i2 = 0; i2 < 4; i2++)
#pragma unroll
                for (int j = 0; j < 4; j++) {
                    float2 s = unpk2(accS[i2][j]);
                    mt[2 * i2]     = fmaxf(mt[2 * i2],     s.x);
                    mt[2 * i2 + 1] = fmaxf(mt[2 * i2 + 1], s.y);
                }
        }

#pragma unroll
        for (int i = 0; i < 8; i++) {
            float v = mt[i];
            v = fmaxf(v, __shfl_xor_sync(0xffffffffu, v, 1));
            v = fmaxf(v, __shfl_xor_sync(0xffffffffu, v, 2));
            v = fmaxf(v, __shfl_xor_sync(0xffffffffu, v, 4));
            v = fmaxf(v, __shfl_xor_sync(0xffffffffu, v, 8));
            const float mn = fmaxf(m[i], v);
            mt[i] = __expf(m[i] - mn);
            m[i] = mn;
            l[i] *= mt[i];
        }
#pragma unroll
        for (int i2 = 0; i2 < 4; i2++) {
            ull al2 = pack2(mt[2 * i2], mt[2 * i2 + 1]);
#pragma unroll
            for (int j = 0; j < 4; j++) mul2(accO[i2][j], al2);
        }

        float lsum[8];
#pragma unroll
        for (int i = 0; i < 8; i++) lsum[i] = 0.f;
#pragma unroll
        for (int j = 0; j < 4; j++) {
            float pv[8];
#pragma unroll
            for (int i2 = 0; i2 < 4; i2++) {
                float2 s = unpk2(accS[i2][j]);
                pv[2 * i2]     = __expf(s.x - m[2 * i2]);
                pv[2 * i2 + 1] = __expf(s.y - m[2 * i2 + 1]);
                lsum[2 * i2]     += pv[2 * i2];
                lsum[2 * i2 + 1] += pv[2 * i2 + 1];
            }
            float* pp = &Pt[(tx * 4 + j) * QST + ty * 8];
            *(float4*)pp       = make_float4(pv[0], pv[1], pv[2], pv[3]);
            *(float4*)(pp + 4) = make_float4(pv[4], pv[5], pv[6], pv[7]);
        }
#pragma unroll
        for (int i = 0; i < 8; i++) {
            float v = lsum[i];
            v += __shfl_xor_sync(0xffffffffu, v, 1);
            v += __shfl_xor_sync(0xffffffffu, v, 2);
            v += __shfl_xor_sync(0xffffffffu, v, 4);
            v += __shfl_xor_sync(0xffffffffu, v, 8);
            l[i] += v;
        }
        __syncthreads();

#pragma unroll 4
        for (int kc = 0; kc < 64; kc++) {
            const float* pr = &Pt[kc * QST + ty * 8];
            ulonglong2 t0 = *(const ulonglong2*)pr;
            ulonglong2 t1 = *(const ulonglong2*)(pr + 4);
            ull p2[4] = { t0.x, t0.y, t1.x, t1.y };
            float4 vv = *(const float4*)&Vs[kc * KST + tx * 4];
            ull v2[4] = { dup2(vv.x), dup2(vv.y), dup2(vv.z), dup2(vv.w) };
#pragma unroll
            for (int i = 0; i < 4; i++)
#pragma unroll
                for (int j = 0; j < 4; j++)
                    fma2(accO[i][j], p2[i], v2[j]);
        }
    }

    // normalize + write bf16 hi/lo [B,S,D] for the O-projection
    float inv[8];
#pragma unroll
    for (int i = 0; i < 8; i++) inv[i] = 1.f / l[i];

#pragma unroll
    for (int i2 = 0; i2 < 4; i2++) {
        float2 v0 = unpk2(accO[i2][0]);
        float2 v1 = unpk2(accO[i2][1]);
        float2 v2 = unpk2(accO[i2][2]);
        float2 v3 = unpk2(accO[i2][3]);
        const float ie = inv[2 * i2], io = inv[2 * i2 + 1];
        float oe[4] = { v0.x * ie, v1.x * ie, v2.x * ie, v3.x * ie };
        float oo[4] = { v0.y * io, v1.y * io, v2.y * io, v3.y * io };
        const int re = q0 + ty * 8 + 2 * i2;
        const size_t off = (size_t)(b * SS + re) * DM + h * DH + tx * 4;
        __nv_bfloat16 h0, h1, l0, l1;
#pragma unroll
        for (int p = 0; p < 2; p++) {
            const float* o = p ? oo : oe;
            const size_t ro = off + (size_t)p * DM;
            bsplit(o[0], h0, l0); bsplit(o[1], h1, l1);
            *(__nv_bfloat162*)(g_ahi + ro) = __nv_bfloat162(h0, h1);
            *(__nv_bfloat162*)(g_alo + ro) = __nv_bfloat162(l0, l1);
            bsplit(o[2], h0, l0); bsplit(o[3], h1, l1);
            *(__nv_bfloat162*)(g_ahi + ro + 2) = __nv_bfloat162(h0, h1);
            *(__nv_bfloat162*)(g_alo + ro + 2) = __nv_bfloat162(l0, l1);
        }
    }
}

// ---------------------------------------------------------------------------
extern "C" void kernel_launch(void* const* d_in, const int* in_sizes, int n_in,
                              void* d_out, int out_size)
{
    const float* x  = (const float*)d_in[0];
    const float* Wq = (const float*)d_in[1];
    const float* bq = (const float*)d_in[2];
    const float* Wk = (const float*)d_in[3];
    const float* bk = (const float*)d_in[4];
    const float* Wv = (const float*)d_in[5];
    const float* bv = (const float*)d_in[6];
    const float* Wo = (const float*)d_in[7];
    float* out = (float*)d_out;

    const int attn_smem = (64 * QST + 64 * KST * 2 + 64 * QST) * (int)sizeof(float);
    cudaFuncSetAttribute(attn_kernel,
                         cudaFuncAttributeMaxDynamicSharedMemorySize, attn_smem);
    cudaFuncSetAttribute(qkv_gemm_mma,
                         cudaFuncAttributeMaxDynamicSharedMemorySize, SMEM_MMA);
    cudaFuncSetAttribute(out_gemm_mma,
                         cudaFuncAttributeMaxDynamicSharedMemorySize, SMEM_MMA);

    split_x<<<MT * DM / 1024, 256>>>(x);
    dim3 gw(DM / 32, DM / 32, 4);
    wsplit<<<gw, 256>>>(Wq, Wk, Wv, Wo);

    dim3 gqkv(DM / 128, MT / 128, 3);
    qkv_gemm_mma<<<gqkv, 256, SMEM_MMA>>>(bq, bk, bv);

    dim3 gattn(SS / 128, NH, BB);
    attn_kernel<<<gattn, 256, attn_smem>>>();

    dim3 gout(DM / 128, MT / 128);
    out_gemm_mma<<<gout, 256, SMEM_MMA>>>(out);
}

// round 7
// speedup vs baseline: 1.0527x; 1.0527x over previous
#include <cuda_runtime.h>
#include <cuda_bf16.h>
#include <cstdint>

// Problem constants
#define DM   1024        // d_model
#define NH   16          // heads
#define DH   64          // head dim
#define BB   2           // batch
#define SS   2048        // seq len
#define MT   (BB*SS)     // total rows = 4096

typedef unsigned long long ull;

// ---------------------------------------------------------------------------
// Scratch (device globals; no allocation allowed)
// ---------------------------------------------------------------------------
__device__ float g_q[BB*NH*SS*DH];               // [B,H,S,Dh] fp32
__device__ float g_k[BB*NH*SS*DH];
__device__ float g_v[BB*NH*SS*DH];
__device__ __nv_bfloat16 g_xhi[MT*DM], g_xlo[MT*DM];        // X split
__device__ __nv_bfloat16 g_wth[4][DM*DM], g_wtl[4][DM*DM];  // W^T splits (q,k,v,o)
__device__ __nv_bfloat16 g_ahi[MT*DM], g_alo[MT*DM];        // attention out split

// ---------------------------------------------------------------------------
// packed f32x2 helpers (attention inner loops)
// ---------------------------------------------------------------------------
__device__ __forceinline__ ull pack2(float lo, float hi) {
    ull r; asm("mov.b64 %0, {%1, %2};" : "=l"(r) : "f"(lo), "f"(hi)); return r;
}
__device__ __forceinline__ ull dup2(float v) { return pack2(v, v); }
__device__ __forceinline__ void fma2(ull& d, ull a, ull b) {
    asm("fma.rn.f32x2 %0, %1, %2, %0;" : "+l"(d) : "l"(a), "l"(b));
}
__device__ __forceinline__ void mul2(ull& d, ull a) {
    asm("mul.rn.f32x2 %0, %0, %1;" : "+l"(d) : "l"(a));
}
__device__ __forceinline__ float2 unpk2(ull v) {
    float2 r; asm("mov.b64 {%0, %1}, %2;" : "=f"(r.x), "=f"(r.y) : "l"(v)); return r;
}

__device__ __forceinline__ uint32_t smem_u32(const void* p) {
    uint32_t a;
    asm("{ .reg .u64 t; cvta.to.shared.u64 t, %1; cvt.u32.u64 %0, t; }" : "=r"(a) : "l"(p));
    return a;
}

__device__ __forceinline__ void bsplit(float x, __nv_bfloat16& h, __nv_bfloat16& l) {
    h = __float2bfloat16(x);
    l = __float2bfloat16(x - __bfloat162float(h));
}

// ---------------------------------------------------------------------------
// mma.sync / ldmatrix / cp.async primitives (sm_80+ features; compile at
// compute_103 — NO tcgen05, which the harness's PTX target rejects)
// ---------------------------------------------------------------------------
#define CPA(dst, src) asm volatile("cp.async.cg.shared.global [%0], [%1], 16;" :: "r"(dst), "l"(src))
#define CPC() asm volatile("cp.async.commit_group;" ::: "memory")
#define CPW(n) asm volatile("cp.async.wait_group %0;" :: "n"(n) : "memory")

__device__ __forceinline__ void ldm4(uint32_t* r, uint32_t addr) {
    asm volatile("ldmatrix.sync.aligned.m8n8.x4.shared.b16 {%0,%1,%2,%3}, [%4];"
                 : "=r"(r[0]), "=r"(r[1]), "=r"(r[2]), "=r"(r[3]) : "r"(addr));
}
__device__ __forceinline__ void mma_bf16(float* d, const uint32_t* a,
                                         uint32_t b0, uint32_t b1) {
    asm volatile(
        "mma.sync.aligned.m16n8k16.row.col.f32.bf16.bf16.f32 "
        "{%0,%1,%2,%3}, {%4,%5,%6,%7}, {%8,%9}, {%0,%1,%2,%3};"
        : "+f"(d[0]), "+f"(d[1]), "+f"(d[2]), "+f"(d[3])
        : "r"(a[0]), "r"(a[1]), "r"(a[2]), "r"(a[3]), "r"(b0), "r"(b1));
}

// ---------------------------------------------------------------------------
// Prep: split X into bf16 hi/lo
// ---------------------------------------------------------------------------
__global__ void __launch_bounds__(256) split_x(const float* __restrict__ X)
{
    const int i = (blockIdx.x * 256 + threadIdx.x) * 4;
    float4 v = *(const float4*)(X + i);
    __nv_bfloat16 h0, h1, h2, h3, l0, l1, l2, l3;
    bsplit(v.x, h0, l0); bsplit(v.y, h1, l1);
    bsplit(v.z, h2, l2); bsplit(v.w, h3, l3);
    *(__nv_bfloat162*)(g_xhi + i)     = __nv_bfloat162(h0, h1);
    *(__nv_bfloat162*)(g_xhi + i + 2) = __nv_bfloat162(h2, h3);
    *(__nv_bfloat162*)(g_xlo + i)     = __nv_bfloat162(l0, l1);
    *(__nv_bfloat162*)(g_xlo + i + 2) = __nv_bfloat162(l2, l3);
}

// ---------------------------------------------------------------------------
// Prep: transpose W [K,N] -> Wt [N,K], split bf16 hi/lo.  z selects matrix.
// ---------------------------------------------------------------------------
__global__ void __launch_bounds__(256) wsplit(
    const float* __restrict__ Wq, const float* __restrict__ Wk,
    const float* __restrict__ Wv, const float* __restrict__ Wo)
{
    __shared__ float t[32][33];
    const int z = blockIdx.z;
    const float* src = (z == 0) ? Wq : (z == 1) ? Wk : (z == 2) ? Wv : Wo;
    const int tx = threadIdx.x & 31;
    const int ty = threadIdx.x >> 5;
    const int n0 = blockIdx.x * 32;
    const int k0 = blockIdx.y * 32;
#pragma unroll
    for (int i = 0; i < 4; i++)
        t[ty + 8 * i][tx] = src[(size_t)(k0 + ty + 8 * i) * DM + n0 + tx];
    __syncthreads();
#pragma unroll
    for (int i = 0; i < 4; i++) {
        const int n = n0 + ty + 8 * i;
        const int k = k0 + tx;
        __nv_bfloat16 h, l;
        bsplit(t[tx][ty + 8 * i], h, l);
        g_wth[z][(size_t)n * DM + k] = h;
        g_wtl[z][(size_t)n * DM + k] = l;
    }
}

// ---------------------------------------------------------------------------
// mma.sync GEMM: C = A @ B^T via bf16-split (hh + hl + lh, fp32 acc).
// CTA 128x128, BK=32, 8 warps (2m x 4n), warp 64x32, cp.async double buffer.
// Smem row stride 40 bf16 (80B, odd multiple of 16B -> conflict-free ldmatrix).
// ---------------------------------------------------------------------------
#define BK      32
#define SAST    40                       // bf16 per smem row (80 bytes)
#define TILE_B  (128 * SAST * 2)         // 10240 B per tile
#define STAGE_B (4 * TILE_B)             // Ahi, Alo, Bhi, Blo = 40960 B
#define SMEM_MMA (2 * STAGE_B)           // 81920 B

template<bool SPLIT_HEAD>
__device__ __forceinline__ void gemm_mma_body(
    const __nv_bfloat16* __restrict__ Ah, const __nv_bfloat16* __restrict__ Al,
    const __nv_bfloat16* __restrict__ Bh, const __nv_bfloat16* __restrict__ Bl,
    const float* __restrict__ bias, float* __restrict__ out)
{
    extern __shared__ char smem[];
    const uint32_t sb = smem_u32(smem);
    const int tid  = threadIdx.x;
    const int lane = tid & 31;
    const int wid  = tid >> 5;
    const int wm   = wid & 1;           // 2 warp rows
    const int wn   = wid >> 1;          // 4 warp cols
    const int m0   = wm * 64;
    const int n0   = wn * 32;
    const int rowBase = blockIdx.y * 128;
    const int colBase = blockIdx.x * 128;

    const __nv_bfloat16* srcs[4] = {
        Ah + (size_t)rowBase * DM, Al + (size_t)rowBase * DM,
        Bh + (size_t)colBase * DM, Bl + (size_t)colBase * DM };

    float acc[4][4][4];
#pragma unroll
    for (int i = 0; i < 4; i++)
#pragma unroll
        for (int j = 0; j < 4; j++)
#pragma unroll
            for (int k = 0; k < 4; k++) acc[i][j][k] = 0.f;

    auto load_stage = [&](int kt, int buf) {
#pragma unroll
        for (int i = 0; i < 8; i++) {
            const int id = tid + 256 * i;          // 0..2047 16B chunks
            const int t  = id >> 9;                // tile 0..3
            const int rr = (id >> 2) & 127;        // row 0..127
            const int cc = id & 3;                 // 16B chunk in row
            const __nv_bfloat16* s = srcs[t] + (size_t)rr * DM + kt * BK + cc * 8;
            const uint32_t d = sb + buf * STAGE_B + t * TILE_B + rr * 80 + cc * 16;
            CPA(d, s);
        }
    };

    load_stage(0, 0); CPC();

    const int lrow = lane & 15;
    const int lchk = (lane >> 4) * 16;

    for (int kt = 0; kt < DM / BK; kt++) {
        if (kt + 1 < DM / BK) { load_stage(kt + 1, (kt + 1) & 1); CPC(); CPW(1); }
        else                  { CPW(0); }
        __syncthreads();

        const uint32_t base = sb + (kt & 1) * STAGE_B;
        const uint32_t aHi = base;
        const uint32_t aLo = base + TILE_B;
        const uint32_t bHi = base + 2 * TILE_B;
        const uint32_t bLo = base + 3 * TILE_B;

#pragma unroll
        for (int sub = 0; sub < 2; sub++) {
            const uint32_t co = sub * 32 + lchk;
            uint32_t a[4][4], bh2[2][4], bl2[2][4];
#pragma unroll
            for (int mt = 0; mt < 4; mt++)
                ldm4(a[mt], aHi + (m0 + mt * 16 + lrow) * 80 + co);
#pragma unroll
            for (int p = 0; p < 2; p++)
                ldm4(bh2[p], bHi + (n0 + p * 16 + lrow) * 80 + co);
            // hi*hi
#pragma unroll
            for (int mt = 0; mt < 4; mt++)
#pragma unroll
                for (int nt = 0; nt < 4; nt++)
                    mma_bf16(acc[mt][nt], a[mt],
                             bh2[nt >> 1][nt & 1], bh2[nt >> 1][2 + (nt & 1)]);
            // hi*lo
#pragma unroll
            for (int p = 0; p < 2; p++)
                ldm4(bl2[p], bLo + (n0 + p * 16 + lrow) * 80 + co);
#pragma unroll
            for (int mt = 0; mt < 4; mt++)
#pragma unroll
                for (int nt = 0; nt < 4; nt++)
                    mma_bf16(acc[mt][nt], a[mt],
                             bl2[nt >> 1][nt & 1], bl2[nt >> 1][2 + (nt & 1)]);
            // lo*hi  (reuse a[] registers for A_lo)
#pragma unroll
            for (int mt = 0; mt < 4; mt++)
                ldm4(a[mt], aLo + (m0 + mt * 16 + lrow) * 80 + co);
#pragma unroll
            for (int mt = 0; mt < 4; mt++)
#pragma unroll
                for (int nt = 0; nt < 4; nt++)
                    mma_bf16(acc[mt][nt], a[mt],
                             bh2[nt >> 1][nt & 1], bh2[nt >> 1][2 + (nt & 1)]);
        }
        __syncthreads();
    }

    // epilogue: d0,d1 -> (row g, col q*2..+1); d2,d3 -> row g+8
    const int g = lane >> 2;
    const int q = lane & 3;
#pragma unroll
    for (int mt = 0; mt < 4; mt++)
#pragma unroll
        for (int nt = 0; nt < 4; nt++) {
            const int c = colBase + n0 + nt * 8 + q * 2;
#pragma unroll
            for (int half = 0; half < 2; half++) {
                const int r = rowBase + m0 + mt * 16 + g + half * 8;
                float2 v = make_float2(acc[mt][nt][half * 2], acc[mt][nt][half * 2 + 1]);
                if (SPLIT_HEAD) {
                    v.x += bias[c]; v.y += bias[c + 1];
                    const int h  = c >> 6;
                    const int dh = c & 63;
                    const int b  = r >> 11;
                    const int s  = r & 2047;
                    *(float2*)&out[((size_t)((b * NH + h) * SS) + s) * DH + dh] = v;
                } else {
                    *(float2*)&out[(size_t)r * DM + c] = v;
                }
            }
        }
}

__global__ void __launch_bounds__(256, 2) qkv_gemm_mma(
    const float* __restrict__ bq, const float* __restrict__ bk,
    const float* __restrict__ bv)
{
    const int z = blockIdx.z;
    const float* bias = (z == 0) ? bq : (z == 1) ? bk : bv;
    float* out = (z == 0) ? g_q : (z == 1) ? g_k : g_v;
    gemm_mma_body<true>(g_xhi, g_xlo, g_wth[z], g_wtl[z], bias, out);
}

__global__ void __launch_bounds__(256, 2) out_gemm_mma(float* __restrict__ out)
{
    gemm_mma_body<false>(g_ahi, g_alo, g_wth[3], g_wtl[3], nullptr, out);
}

// ---------------------------------------------------------------------------
// Flash attention (causal, online softmax), FFMA2 register-blocked.
// Br=128, Bc=64, 256 threads; epilogue writes bf16 hi/lo for the O-projection.
// ---------------------------------------------------------------------------
#define QST 132
#define KST 68

__global__ void __launch_bounds__(256, 2) attn_kernel()
{
    extern __shared__ float sm[];
    float* Qt = sm;                       // 64 x 132 (d-major, transposed)
    float* Kt = sm + 64 * QST;            // 64 x 68
    float* Vs = Kt + 64 * KST;            // 64 x 68
    float* Pt = Vs + 64 * KST;            // 64 x 132

    const int tid = threadIdx.x;
    const int qb  = (gridDim.x - 1) - blockIdx.x;
    const int h   = blockIdx.y;
    const int b   = blockIdx.z;
    const int tx  = tid & 15;
    const int ty  = tid >> 4;

    const size_t head_off = (size_t)(b * NH + h) * SS * DH;
    const float* qbase = g_q + head_off;
    const float* kbase = g_k + head_off;
    const float* vbase = g_v + head_off;
    const int q0 = qb * 128;

#pragma unroll
    for (int i = 0; i < 8; i++) {
        const int f  = tid + 256 * i;
        const int r  = f >> 4;
        const int c4 = (f & 15) << 2;
        float4 v = *(const float4*)(qbase + (size_t)(q0 + r) * DH + c4);
        Qt[(c4 + 0) * QST + r] = v.x * 0.125f;
        Qt[(c4 + 1) * QST + r] = v.y * 0.125f;
        Qt[(c4 + 2) * QST + r] = v.z * 0.125f;
        Qt[(c4 + 3) * QST + r] = v.w * 0.125f;
    }

    ull accO[4][4];
#pragma unroll
    for (int i = 0; i < 4; i++)
#pragma unroll
        for (int j = 0; j < 4; j++) accO[i][j] = 0ull;
    float m[8], l[8];
#pragma unroll
    for (int i = 0; i < 8; i++) { m[i] = -1e30f; l[i] = 0.f; }

    const int kb_end = 2 * qb + 1;
    for (int kb = 0; kb <= kb_end; kb++) {
        __syncthreads();
        const int k0 = kb * 64;
#pragma unroll
        for (int i = 0; i < 4; i++) {
            const int f  = tid + 256 * i;
            const int r  = f >> 4;
            const int c4 = (f & 15) << 2;
            const size_t goff = (size_t)(k0 + r) * DH + c4;
            float4 kv = *(const float4*)(kbase + goff);
            Kt[(c4 + 0) * KST + r] = kv.x;
            Kt[(c4 + 1) * KST + r] = kv.y;
            Kt[(c4 + 2) * KST + r] = kv.z;
            Kt[(c4 + 3) * KST + r] = kv.w;
            *(float4*)&Vs[r * KST + c4] = *(const float4*)(vbase + goff);
        }
        __syncthreads();

        ull accS[4][4];
#pragma unroll
        for (int i = 0; i < 4; i++)
#pragma unroll
            for (int j = 0; j < 4; j++) accS[i][j] = 0ull;

#pragma unroll 4
        for (int d = 0; d < 64; d++) {
            const float* qr = &Qt[d * QST + ty * 8];
            ulonglong2 t0 = *(const ulonglong2*)qr;
            ulonglong2 t1 = *(const ulonglong2*)(qr + 4);
            ull a2[4] = { t0.x, t0.y, t1.x, t1.y };
            float4 kv = *(const float4*)&Kt[d * KST + tx * 4];
            ull k2[4] = { dup2(kv.x), dup2(kv.y), dup2(kv.z), dup2(kv.w) };
#pragma unroll
            for (int i = 0; i < 4; i++)
#pragma unroll
                for (int j = 0; j < 4; j++)
                    fma2(accS[i][j], a2[i], k2[j]);
        }

        const int rel = k0 - q0;
        float mt[8];
#pragma unroll
        for (int i = 0; i < 8; i++) mt[i] = -1e30f;

        if (rel >= -63) {
#pragma unroll
            for (int i2 = 0; i2 < 4; i2++) {
                const int re = ty * 8 + 2 * i2;
#pragma unroll
                for (int j = 0; j < 4; j++) {
                    float2 s = unpk2(accS[i2][j]);
                    const int c = rel + tx * 4 + j;
                    if (c > re)     s.x = -1e30f;
                    if (c > re + 1) s.y = -1e30f;
                    accS[i2][j] = pack2(s.x, s.y);
                    mt[2 * i2]     = fmaxf(mt[2 * i2],     s.x);
                    mt[2 * i2 + 1] = fmaxf(mt[2 * i2 + 1], s.y);
                }
            }
        } else {
#pragma unroll
            for (int i2 = 0; i2 < 4; i2++)
#pragma unroll
                for (int j = 0; j < 4; j++) {
                    float2 s = unpk2(accS[i2][j]);
                    mt[2 * i2]     = fmaxf(mt[2 * i2],     s.x);
                    mt[2 * i2 + 1] = fmaxf(mt[2 * i2 + 1], s.y);
                }
        }

#pragma unroll
        for (int i = 0; i < 8; i++) {
            float v = mt[i];
            v = fmaxf(v, __shfl_xor_sync(0xffffffffu, v, 1));
            v = fmaxf(v, __shfl_xor_sync(0xffffffffu, v, 2));
            v = fmaxf(v, __shfl_xor_sync(0xffffffffu, v, 4));
            v = fmaxf(v, __shfl_xor_sync(0xffffffffu, v, 8));
            const float mn = fmaxf(m[i], v);
            mt[i] = __expf(m[i] - mn);
            m[i] = mn;
            l[i] *= mt[i];
        }
#pragma unroll
        for (int i2 = 0; i2 < 4; i2++) {
            ull al2 = pack2(mt[2 * i2], mt[2 * i2 + 1]);
#pragma unroll
            for (int j = 0; j < 4; j++) mul2(accO[i2][j], al2);
        }

        float lsum[8];
#pragma unroll
        for (int i = 0; i < 8; i++) lsum[i] = 0.f;
#pragma unroll
        for (int j = 0; j < 4; j++) {
            float pv[8];
#pragma unroll
            for (int i2 = 0; i2 < 4; i2++) {
                float2 s = unpk2(accS[i2][j]);
                pv[2 * i2]     = __expf(s.x - m[2 * i2]);
                pv[2 * i2 + 1] = __expf(s.y - m[2 * i2 + 1]);
                lsum[2 * i2]     += pv[2 * i2];
                lsum[2 * i2 + 1] += pv[2 * i2 + 1];
            }
            float* pp = &Pt[(tx * 4 + j) * QST + ty * 8];
            *(float4*)pp       = make_float4(pv[0], pv[1], pv[2], pv[3]);
            *(float4*)(pp + 4) = make_float4(pv[4], pv[5], pv[6], pv[7]);
        }
#pragma unroll
        for (int i = 0; i < 8; i++) {
            float v = lsum[i];
            v += __shfl_xor_sync(0xffffffffu, v, 1);
            v += __shfl_xor_sync(0xffffffffu, v, 2);
            v += __shfl_xor_sync(0xffffffffu, v, 4);
            v += __shfl_xor_sync(0xffffffffu, v, 8);
            l[i] += v;
        }
        __syncthreads();

#pragma unroll 4
        for (int kc = 0; kc < 64; kc++) {
            const float* pr = &Pt[kc * QST + ty * 8];
            ulonglong2 t0 = *(const ulonglong2*)pr;
            ulonglong2 t1 = *(const ulonglong2*)(pr + 4);
            ull p2[4] = { t0.x, t0.y, t1.x, t1.y };
            float4 vv = *(const float4*)&Vs[kc * KST + tx * 4];
            ull v2[4] = { dup2(vv.x), dup2(vv.y), dup2(vv.z), dup2(vv.w) };
#pragma unroll
            for (int i = 0; i < 4; i++)
#pragma unroll
                for (int j = 0; j < 4; j++)
                    fma2(accO[i][j], p2[i], v2[j]);
        }
    }

    // normalize + write bf16 hi/lo [B,S,D] for the O-projection
    float inv[8];
#pragma unroll
    for (int i = 0; i < 8; i++) inv[i] = 1.f / l[i];

#pragma unroll
    for (int i2 = 0; i2 < 4; i2++) {
        float2 v0 = unpk2(accO[i2][0]);
        float2 v1 = unpk2(accO[i2][1]);
        float2 v2 = unpk2(accO[i2][2]);
        float2 v3 = unpk2(accO[i2][3]);
        const float ie = inv[2 * i2], io = inv[2 * i2 + 1];
        float oe[4] = { v0.x * ie, v1.x * ie, v2.x * ie, v3.x * ie };
        float oo[4] = { v0.y * io, v1.y * io, v2.y * io, v3.y * io };
        const int re = q0 + ty * 8 + 2 * i2;
        const size_t off = (size_t)(b * SS + re) * DM + h * DH + tx * 4;
        __nv_bfloat16 h0, h1, l0, l1;
#pragma unroll
        for (int p = 0; p < 2; p++) {
            const float* o = p ? oo : oe;
            const size_t ro = off + (size_t)p * DM;
            bsplit(o[0], h0, l0); bsplit(o[1], h1, l1);
            *(__nv_bfloat162*)(g_ahi + ro) = __nv_bfloat162(h0, h1);
            *(__nv_bfloat162*)(g_alo + ro) = __nv_bfloat162(l0, l1);
            bsplit(o[2], h0, l0); bsplit(o[3], h1, l1);
            *(__nv_bfloat162*)(g_ahi + ro + 2) = __nv_bfloat162(h0, h1);
            *(__nv_bfloat162*)(g_alo + ro + 2) = __nv_bfloat162(l0, l1);
        }
    }
}

// ---------------------------------------------------------------------------
extern "C" void kernel_launch(void* const* d_in, const int* in_sizes, int n_in,
                              void* d_out, int out_size)
{
    const float* x  = (const float*)d_in[0];
    const float* Wq = (const float*)d_in[1];
    const float* bq = (const float*)d_in[2];
    const float* Wk = (const float*)d_in[3];
    const float* bk = (const float*)d_in[4];
    const float* Wv = (const float*)d_in[5];
    const float* bv = (const float*)d_in[6];
    const float* Wo = (const float*)d_in[7];
    float* out = (float*)d_out;

    const int attn_smem = (64 * QST + 64 * KST * 2 + 64 * QST) * (int)sizeof(float);
    cudaFuncSetAttribute(attn_kernel,
                         cudaFuncAttributeMaxDynamicSharedMemorySize, attn_smem);
    cudaFuncSetAttribute(qkv_gemm_mma,
                         cudaFuncAttributeMaxDynamicSharedMemorySize, SMEM_MMA);
    cudaFuncSetAttribute(out_gemm_mma,
                         cudaFuncAttributeMaxDynamicSharedMemorySize, SMEM_MMA);

    split_x<<<MT * DM / 1024, 256>>>(x);
    dim3 gw(DM / 32, DM / 32, 4);
    wsplit<<<gw, 256>>>(Wq, Wk, Wv, Wo);

    dim3 gqkv(DM / 128, MT / 128, 3);
    qkv_gemm_mma<<<gqkv, 256, SMEM_MMA>>>(bq, bk, bv);

    dim3 gattn(SS / 128, NH, BB);
    attn_kernel<<<gattn, 256, attn_smem>>>();

    dim3 gout(DM / 128, MT / 128);
    out_gemm_mma<<<gout, 256, SMEM_MMA>>>(out);
}